// round 1
// baseline (speedup 1.0000x reference)
#include <cuda_runtime.h>
#include <cuda_fp16.h>
#include <cstdint>

// Problem shape (fixed for this dataset)
#define BQ 2
#define SQ 2048
#define KD 4096
#define ND 11008
#define MD (BQ*SQ)   // 4096

// Pre-converted fp16 operands (scratch via __device__ globals — allocation-free rule)
__device__ __half g_xh[(size_t)MD * KD];   // 32 MB
__device__ __half g_wh[(size_t)ND * KD];   // 86 MB, dequantized: (q + off[n]) * scale[n]

// ---------------------------------------------------------------------------
// Prep kernels
// ---------------------------------------------------------------------------
__global__ void prep_x_kernel(const float* __restrict__ x) {
    size_t n4 = (size_t)MD * KD / 4;
    for (size_t i = (size_t)blockIdx.x * blockDim.x + threadIdx.x; i < n4;
         i += (size_t)gridDim.x * blockDim.x) {
        float4 v = reinterpret_cast<const float4*>(x)[i];
        __half2 h[2];
        h[0] = __floats2half2_rn(v.x, v.y);
        h[1] = __floats2half2_rn(v.z, v.w);
        reinterpret_cast<uint2*>(g_xh)[i] = *reinterpret_cast<uint2*>(h);
    }
}

__global__ void prep_w_kernel(const int* __restrict__ w,
                              const float* __restrict__ scale,
                              const float* __restrict__ off) {
    size_t n4 = (size_t)ND * KD / 4;
    for (size_t i = (size_t)blockIdx.x * blockDim.x + threadIdx.x; i < n4;
         i += (size_t)gridDim.x * blockDim.x) {
        int4 q = reinterpret_cast<const int4*>(w)[i];
        int n = (int)(i / (KD / 4));            // K divisible by 4: same row for all 4
        float s = __ldg(scale + n);
        float o = __ldg(off + n);
        __half2 h[2];
        h[0] = __floats2half2_rn(((float)q.x + o) * s, ((float)q.y + o) * s);
        h[1] = __floats2half2_rn(((float)q.z + o) * s, ((float)q.w + o) * s);
        reinterpret_cast<uint2*>(g_wh)[i] = *reinterpret_cast<uint2*>(h);
    }
}

// ---------------------------------------------------------------------------
// fp16 GEMM: out[m][n] = sum_k xh[m][k] * wh[n][k] + bias[n]
// BM=128, BN=128, BK=32, 256 threads (8 warps as 2(m) x 4(n), warp tile 64x32)
// cp.async double-buffered, XOR-swizzled smem, ldmatrix.x4, mma.m16n8k16
// ---------------------------------------------------------------------------
#define BM 128
#define BN 128
#define BK 32
#define GROUP_M 8

__device__ __forceinline__ void cp_async16(uint32_t saddr, const void* gptr) {
    asm volatile("cp.async.cg.shared.global [%0], [%1], 16;\n" ::"r"(saddr), "l"(gptr));
}
__device__ __forceinline__ void cp_commit() {
    asm volatile("cp.async.commit_group;\n" ::: "memory");
}
__device__ __forceinline__ void ldm_x4(uint32_t* r, uint32_t addr) {
    asm volatile("ldmatrix.sync.aligned.m8n8.x4.shared.b16 {%0,%1,%2,%3}, [%4];\n"
                 : "=r"(r[0]), "=r"(r[1]), "=r"(r[2]), "=r"(r[3]) : "r"(addr));
}
__device__ __forceinline__ void mma16816(float* c, const uint32_t* a, const uint32_t* b) {
    asm volatile(
        "mma.sync.aligned.m16n8k16.row.col.f32.f16.f16.f32 "
        "{%0,%1,%2,%3},{%4,%5,%6,%7},{%8,%9},{%0,%1,%2,%3};\n"
        : "+f"(c[0]), "+f"(c[1]), "+f"(c[2]), "+f"(c[3])
        : "r"(a[0]), "r"(a[1]), "r"(a[2]), "r"(a[3]), "r"(b[0]), "r"(b[1]));
}

// Swizzled byte offset inside one [rows][32 halves] tile.
// 16B chunk c in row m goes to chunk c ^ ((m>>1)&3): 8 ldmatrix rows hit 8
// distinct 16B phases mod 128B -> conflict-free for both cp.async and ldmatrix.
__device__ __forceinline__ uint32_t swz(int row, int chunk) {
    return (uint32_t)(row * 64 + ((chunk ^ ((row >> 1) & 3)) << 4));
}

__global__ void __launch_bounds__(256, 1)
gemm_f16_kernel(const float* __restrict__ bias, float* __restrict__ out) {
    constexpr int num_m = MD / BM;  // 32
    constexpr int num_n = ND / BN;  // 86
    constexpr int KT = KD / BK;     // 128

    // Grouped-M rasterization for L2 reuse
    int pid = blockIdx.x;
    int npg = GROUP_M * num_n;
    int gidg = pid / npg;
    int first_m = gidg * GROUP_M;
    int gm = min(num_m - first_m, GROUP_M);
    int pin = pid % npg;
    int pm = first_m + (pin % gm);
    int pn = pin / gm;
    const int m0 = pm * BM, n0 = pn * BN;

    __shared__ __half As[2][BM * BK];
    __shared__ __half Bs[2][BN * BK];

    const int tid = threadIdx.x;
    const int warp = tid >> 5, lane = tid & 31;
    const int wm = (warp >> 2) * 64;  // 0 or 64
    const int wn = (warp & 3) * 32;   // 0..96

    const uint32_t sA = (uint32_t)__cvta_generic_to_shared(&As[0][0]);
    const uint32_t sB = (uint32_t)__cvta_generic_to_shared(&Bs[0][0]);
    constexpr uint32_t STG = BM * BK * 2;  // 8192 bytes per stage

    const __half* gA = g_xh + (size_t)m0 * KD;
    const __half* gB = g_wh + (size_t)n0 * KD;

    // cp.async assignment: 512 16B-chunks per tile, 2 per thread per tile
    const int r0c = (tid) >> 2,        c0c = tid & 3;
    const int r1c = (tid + 256) >> 2,  c1c = tid & 3;  // (tid+256)&3 == tid&3

    float acc[4][4][4];
#pragma unroll
    for (int i = 0; i < 4; i++)
#pragma unroll
        for (int j = 0; j < 4; j++)
#pragma unroll
            for (int v = 0; v < 4; v++) acc[i][j][v] = 0.f;

    auto load_stage = [&](int st, int k0) {
        cp_async16(sA + st * STG + swz(r0c, c0c), gA + (size_t)r0c * KD + k0 + c0c * 8);
        cp_async16(sA + st * STG + swz(r1c, c1c), gA + (size_t)r1c * KD + k0 + c1c * 8);
        cp_async16(sB + st * STG + swz(r0c, c0c), gB + (size_t)r0c * KD + k0 + c0c * 8);
        cp_async16(sB + st * STG + swz(r1c, c1c), gB + (size_t)r1c * KD + k0 + c1c * 8);
        cp_commit();
    };

    load_stage(0, 0);

    // ldmatrix lane->address mappings (constant across k loop)
    const int a_row = lane & 15;            // row within m16
    const int a_chx = lane >> 4;            // +0/+1 chunk (k / k+8)
    const int b_row = ((lane >> 4) << 3) + (lane & 7);  // n within n16
    const int b_chx = (lane >> 3) & 1;      // k / k+8

    for (int kt = 0; kt < KT; kt++) {
        if (kt + 1 < KT) load_stage((kt + 1) & 1, (kt + 1) * BK);
        if (kt + 1 < KT) { asm volatile("cp.async.wait_group 1;\n" ::: "memory"); }
        else             { asm volatile("cp.async.wait_group 0;\n" ::: "memory"); }
        __syncthreads();

        const int st = kt & 1;
        const uint32_t baseA = sA + st * STG;
        const uint32_t baseB = sB + st * STG;
#pragma unroll
        for (int ks = 0; ks < 2; ks++) {  // two k16 steps in BK=32
            uint32_t a[4][4];
#pragma unroll
            for (int mf = 0; mf < 4; mf++) {
                int m = wm + mf * 16 + a_row;
                ldm_x4(a[mf], baseA + swz(m, ks * 2 + a_chx));
            }
            uint32_t b[4][2];
#pragma unroll
            for (int nf2 = 0; nf2 < 2; nf2++) {
                int n = wn + nf2 * 16 + b_row;
                uint32_t r[4];
                ldm_x4(r, baseB + swz(n, ks * 2 + b_chx));
                b[nf2 * 2][0] = r[0];  b[nf2 * 2][1] = r[1];
                b[nf2 * 2 + 1][0] = r[2]; b[nf2 * 2 + 1][1] = r[3];
            }
#pragma unroll
            for (int mf = 0; mf < 4; mf++)
#pragma unroll
                for (int nf = 0; nf < 4; nf++) mma16816(acc[mf][nf], a[mf], b[nf]);
        }
        __syncthreads();
    }

    // Epilogue: + bias, fp32 out
#pragma unroll
    for (int nf = 0; nf < 4; nf++) {
        int n = n0 + wn + nf * 8 + ((lane & 3) << 1);
        float2 bv = *reinterpret_cast<const float2*>(bias + n);
#pragma unroll
        for (int mf = 0; mf < 4; mf++) {
            int m = m0 + wm + mf * 16 + (lane >> 2);
            float2 v0 = make_float2(acc[mf][nf][0] + bv.x, acc[mf][nf][1] + bv.y);
            float2 v1 = make_float2(acc[mf][nf][2] + bv.x, acc[mf][nf][3] + bv.y);
            *reinterpret_cast<float2*>(out + (size_t)m * ND + n) = v0;
            *reinterpret_cast<float2*>(out + (size_t)(m + 8) * ND + n) = v1;
        }
    }
}

// ---------------------------------------------------------------------------
extern "C" void kernel_launch(void* const* d_in, const int* in_sizes, int n_in,
                              void* d_out, int out_size) {
    const float* x     = (const float*)d_in[0];
    const int*   w     = (const int*)d_in[1];
    const float* scale = (const float*)d_in[2];
    const float* off   = (const float*)d_in[3];
    const float* bias  = (const float*)d_in[4];
    float* out = (float*)d_out;

    prep_x_kernel<<<2048, 256>>>(x);
    prep_w_kernel<<<4096, 256>>>(w, scale, off);
    gemm_f16_kernel<<<(MD / BM) * (ND / BN), 256>>>(bias, out);
}

// round 9
// speedup vs baseline: 1.2958x; 1.2958x over previous
#include <cuda_runtime.h>
#include <cuda_fp16.h>
#include <cstdint>

// Problem shape (fixed for this dataset)
#define BQ 2
#define SQ 2048
#define KD 4096
#define ND 11008
#define MD (BQ*SQ)   // 4096

// Pre-converted fp16 operands (scratch via __device__ globals — allocation-free rule)
__device__ __half g_xh[(size_t)MD * KD];   // 32 MB
__device__ __half g_wh[(size_t)ND * KD];   // 86 MB, dequantized: (q + off[n]) * scale[n]

// ---------------------------------------------------------------------------
// Prep kernels
// ---------------------------------------------------------------------------
__global__ void prep_x_kernel(const float* __restrict__ x) {
    size_t n4 = (size_t)MD * KD / 4;
    for (size_t i = (size_t)blockIdx.x * blockDim.x + threadIdx.x; i < n4;
         i += (size_t)gridDim.x * blockDim.x) {
        float4 v = reinterpret_cast<const float4*>(x)[i];
        __half2 h[2];
        h[0] = __floats2half2_rn(v.x, v.y);
        h[1] = __floats2half2_rn(v.z, v.w);
        reinterpret_cast<uint2*>(g_xh)[i] = *reinterpret_cast<uint2*>(h);
    }
}

__global__ void prep_w_kernel(const int* __restrict__ w,
                              const float* __restrict__ scale,
                              const float* __restrict__ off) {
    size_t n4 = (size_t)ND * KD / 4;
    for (size_t i = (size_t)blockIdx.x * blockDim.x + threadIdx.x; i < n4;
         i += (size_t)gridDim.x * blockDim.x) {
        int4 q = reinterpret_cast<const int4*>(w)[i];
        int n = (int)(i / (KD / 4));
        float s = __ldg(scale + n);
        float o = __ldg(off + n);
        __half2 h[2];
        h[0] = __floats2half2_rn(((float)q.x + o) * s, ((float)q.y + o) * s);
        h[1] = __floats2half2_rn(((float)q.z + o) * s, ((float)q.w + o) * s);
        reinterpret_cast<uint2*>(g_wh)[i] = *reinterpret_cast<uint2*>(h);
    }
}

// ---------------------------------------------------------------------------
// HMMA GEMM (mma.sync works on base sm_100; tcgen05 does NOT — ptxas target).
// out[m][n] = sum_k xh[m][k]*wh[n][k] + bias[n]
// BM=128, BN=256, BK=32, 256 threads (8 warps as 2(m) x 4(n)), warp tile 64x64.
// 4-stage cp.async ring, ONE __syncthreads per k-step, uniform group counting
// via empty commit_group at the tail. XOR-swizzled smem + ldmatrix.x4.
// ---------------------------------------------------------------------------
#define BM 128
#define BN 256
#define BK 32
#define STAGES 4
#define KT (KD / BK)            // 128
#define A_BYTES (BM * BK * 2)   // 8192
#define B_BYTES (BN * BK * 2)   // 16384
#define STAGE_BYTES (A_BYTES + B_BYTES)  // 24576

__device__ __forceinline__ void cp_async16(uint32_t saddr, const void* gptr) {
    asm volatile("cp.async.cg.shared.global [%0], [%1], 16;" :: "r"(saddr), "l"(gptr) : "memory");
}
__device__ __forceinline__ void cp_commit() {
    asm volatile("cp.async.commit_group;" ::: "memory");
}
__device__ __forceinline__ void ldm_x4(uint32_t* r, uint32_t addr) {
    asm volatile("ldmatrix.sync.aligned.m8n8.x4.shared.b16 {%0,%1,%2,%3}, [%4];"
                 : "=r"(r[0]), "=r"(r[1]), "=r"(r[2]), "=r"(r[3]) : "r"(addr));
}
__device__ __forceinline__ void mma16816(float* c, const uint32_t* a, const uint32_t* b) {
    asm volatile(
        "mma.sync.aligned.m16n8k16.row.col.f32.f16.f16.f32 "
        "{%0,%1,%2,%3},{%4,%5,%6,%7},{%8,%9},{%0,%1,%2,%3};"
        : "+f"(c[0]), "+f"(c[1]), "+f"(c[2]), "+f"(c[3])
        : "r"(a[0]), "r"(a[1]), "r"(a[2]), "r"(a[3]), "r"(b[0]), "r"(b[1]));
}

// Swizzled byte offset inside one [rows][32 halves] tile (64B rows, 4x16B chunks).
// Chunk c of row m -> c ^ ((m>>1)&3): proven conflict-shape in the R1 kernel.
__device__ __forceinline__ uint32_t swz(int row, int chunk) {
    return (uint32_t)(row * 64 + ((chunk ^ ((row >> 1) & 3)) << 4));
}

__global__ void __launch_bounds__(256)
gemm_f16_kernel(const float* __restrict__ bias, float* __restrict__ out) {
    extern __shared__ __align__(128) char dsm_raw[];
    // round base up to 1KB so the swizzle math is phase-aligned
    uint32_t dbase;
    {
        uint32_t a;
        asm("{ .reg .u64 t; cvta.to.shared.u64 t, %1; cvt.u32.u64 %0, t; }"
            : "=r"(a) : "l"(dsm_raw));
        dbase = (a + 1023u) & ~1023u;
    }

    // 32 m-tiles fast, 43 n-tiles slow: one wave shares A (32MB) + few B slabs in L2
    const int pm = blockIdx.x & 31;
    const int pn = blockIdx.x >> 5;
    const int m0 = pm * BM, n0 = pn * BN;

    const int tid = threadIdx.x;
    const int warp = tid >> 5, lane = tid & 31;
    const int wm = (warp >> 2) * 64;  // 0 or 64
    const int wn = (warp & 3) * 64;   // 0,64,128,192

    const __half* gA = g_xh + (size_t)m0 * KD;
    const __half* gB = g_wh + (size_t)n0 * KD;

    // cp.async assignment (per stage): A = 512 chunks (2/thread), B = 1024 (4/thread)
    const int rA = tid >> 2;        // 0..63
    const int cC = tid & 3;         // chunk col 0..3
    const int rB = tid >> 2;        // 0..63

    auto load_stage = [&](int kt) {
        const uint32_t sb = dbase + (kt % STAGES) * STAGE_BYTES;
        const int k0 = kt * BK;
        // A: rows rA, rA+64
        cp_async16(sb + swz(rA, cC),      gA + (size_t)rA * KD + k0 + cC * 8);
        cp_async16(sb + swz(rA + 64, cC), gA + (size_t)(rA + 64) * KD + k0 + cC * 8);
        // B: rows rB, +64, +128, +192
        const uint32_t bb = sb + A_BYTES;
#pragma unroll
        for (int i = 0; i < 4; i++) {
            cp_async16(bb + swz(rB + i * 64, cC),
                       gB + (size_t)(rB + i * 64) * KD + k0 + cC * 8);
        }
        cp_commit();
    };

    float acc[4][8][4];
#pragma unroll
    for (int i = 0; i < 4; i++)
#pragma unroll
        for (int j = 0; j < 8; j++)
#pragma unroll
            for (int v = 0; v < 4; v++) acc[i][j][v] = 0.f;

    // Prologue: stages 0..S-2 in flight (3 committed groups)
    for (int p = 0; p < STAGES - 1; p++) load_stage(p);

    // ldmatrix lane->address mappings (constant across k loop) — proven in R1
    const int a_row = lane & 15;
    const int a_chx = lane >> 4;
    const int b_row = ((lane >> 4) << 3) + (lane & 7);
    const int b_chx = (lane >> 3) & 1;

    for (int kt = 0; kt < KT; kt++) {
        // pending = S-1 groups; wait to S-2 => stage kt complete
        asm volatile("cp.async.wait_group %0;" :: "n"(STAGES - 2) : "memory");
        __syncthreads();
        // issue next load AFTER the sync (its target buffer was read in iter kt-1)
        if (kt + STAGES - 1 < KT) load_stage(kt + STAGES - 1);
        else cp_commit();  // empty group keeps pending-count arithmetic uniform

        const uint32_t sb = dbase + (kt % STAGES) * STAGE_BYTES;
        const uint32_t bb = sb + A_BYTES;
#pragma unroll
        for (int ks = 0; ks < 2; ks++) {  // two k16 steps in BK=32
            uint32_t a[4][4];
#pragma unroll
            for (int mf = 0; mf < 4; mf++)
                ldm_x4(a[mf], sb + swz(wm + mf * 16 + a_row, ks * 2 + a_chx));
            uint32_t b[8][2];
#pragma unroll
            for (int nf2 = 0; nf2 < 4; nf2++) {
                uint32_t r[4];
                ldm_x4(r, bb + swz(wn + nf2 * 16 + b_row, ks * 2 + b_chx));
                b[nf2 * 2][0] = r[0];     b[nf2 * 2][1] = r[1];
                b[nf2 * 2 + 1][0] = r[2]; b[nf2 * 2 + 1][1] = r[3];
            }
#pragma unroll
            for (int mf = 0; mf < 4; mf++)
#pragma unroll
                for (int nf = 0; nf < 8; nf++) mma16816(acc[mf][nf], a[mf], b[nf]);
        }
    }

    // Epilogue: + bias, fp32 out (frag (mf,nf): rows +{0,8}, cols lane%4*2)
#pragma unroll
    for (int nf = 0; nf < 8; nf++) {
        const int n = n0 + wn + nf * 8 + ((lane & 3) << 1);
        const float2 bv = *reinterpret_cast<const float2*>(bias + n);
#pragma unroll
        for (int mf = 0; mf < 4; mf++) {
            const int m = m0 + wm + mf * 16 + (lane >> 2);
            float2 v0 = make_float2(acc[mf][nf][0] + bv.x, acc[mf][nf][1] + bv.y);
            float2 v1 = make_float2(acc[mf][nf][2] + bv.x, acc[mf][nf][3] + bv.y);
            *reinterpret_cast<float2*>(out + (size_t)m * ND + n) = v0;
            *reinterpret_cast<float2*>(out + (size_t)(m + 8) * ND + n) = v1;
        }
    }
}

// ---------------------------------------------------------------------------
extern "C" void kernel_launch(void* const* d_in, const int* in_sizes, int n_in,
                              void* d_out, int out_size) {
    const float* x     = (const float*)d_in[0];
    const int*   w     = (const int*)d_in[1];
    const float* scale = (const float*)d_in[2];
    const float* off   = (const float*)d_in[3];
    const float* bias  = (const float*)d_in[4];
    float* out = (float*)d_out;

    prep_x_kernel<<<2048, 256>>>(x);
    prep_w_kernel<<<4096, 256>>>(w, scale, off);

    const int dyn_smem = STAGES * STAGE_BYTES + 1024;  // 99328 B
    cudaFuncSetAttribute(gemm_f16_kernel, cudaFuncAttributeMaxDynamicSharedMemorySize, dyn_smem);
    gemm_f16_kernel<<<(MD / BM) * (ND / BN), 256, dyn_smem>>>(bias, out);
}

// round 10
// speedup vs baseline: 1.5260x; 1.1777x over previous
#include <cuda_runtime.h>
#include <cuda_fp16.h>
#include <cstdint>

// Problem shape (fixed for this dataset)
#define BQ 2
#define SQ 2048
#define KD 4096
#define ND 11008
#define MD (BQ*SQ)   // 4096

// Pre-converted fp16 operands (scratch via __device__ globals — allocation-free rule)
__device__ __half g_xh[(size_t)MD * KD];   // 32 MB
__device__ __half g_wh[(size_t)ND * KD];   // 86 MB, dequantized: (q + off[n]) * scale[n]

// ---------------------------------------------------------------------------
// Prep kernels
// ---------------------------------------------------------------------------
__global__ void prep_x_kernel(const float* __restrict__ x) {
    size_t n4 = (size_t)MD * KD / 4;
    for (size_t i = (size_t)blockIdx.x * blockDim.x + threadIdx.x; i < n4;
         i += (size_t)gridDim.x * blockDim.x) {
        float4 v = reinterpret_cast<const float4*>(x)[i];
        __half2 h[2];
        h[0] = __floats2half2_rn(v.x, v.y);
        h[1] = __floats2half2_rn(v.z, v.w);
        reinterpret_cast<uint2*>(g_xh)[i] = *reinterpret_cast<uint2*>(h);
    }
}

__global__ void prep_w_kernel(const int* __restrict__ w,
                              const float* __restrict__ scale,
                              const float* __restrict__ off) {
    size_t n4 = (size_t)ND * KD / 4;
    for (size_t i = (size_t)blockIdx.x * blockDim.x + threadIdx.x; i < n4;
         i += (size_t)gridDim.x * blockDim.x) {
        int4 q = reinterpret_cast<const int4*>(w)[i];
        int n = (int)(i / (KD / 4));
        float s = __ldg(scale + n);
        float o = __ldg(off + n);
        __half2 h[2];
        h[0] = __floats2half2_rn(((float)q.x + o) * s, ((float)q.y + o) * s);
        h[1] = __floats2half2_rn(((float)q.z + o) * s, ((float)q.w + o) * s);
        reinterpret_cast<uint2*>(g_wh)[i] = *reinterpret_cast<uint2*>(h);
    }
}

// ---------------------------------------------------------------------------
// HMMA GEMM, 2 CTAs/SM for barrier overlap.
// out[m][n] = sum_k xh[m][k]*wh[n][k] + bias[n]
// CTA: 128 threads (4 warps as 2(m) x 2(n)), BM=128, BN=128, BK=32,
// warp tile 64x64 (32 FLOP/smem-byte balance point). 5-stage cp.async ring,
// ONE __syncthreads per k-step, uniform group counting via tail empty commits.
// ---------------------------------------------------------------------------
#define BM 128
#define BN 128
#define BK 32
#define STAGES 5
#define KT (KD / BK)            // 128
#define A_BYTES (BM * BK * 2)   // 8192
#define B_BYTES (BN * BK * 2)   // 8192
#define STAGE_BYTES (A_BYTES + B_BYTES)  // 16384

__device__ __forceinline__ void cp_async16(uint32_t saddr, const void* gptr) {
    asm volatile("cp.async.cg.shared.global [%0], [%1], 16;" :: "r"(saddr), "l"(gptr) : "memory");
}
__device__ __forceinline__ void cp_commit() {
    asm volatile("cp.async.commit_group;" ::: "memory");
}
__device__ __forceinline__ void ldm_x4(uint32_t* r, uint32_t addr) {
    asm volatile("ldmatrix.sync.aligned.m8n8.x4.shared.b16 {%0,%1,%2,%3}, [%4];"
                 : "=r"(r[0]), "=r"(r[1]), "=r"(r[2]), "=r"(r[3]) : "r"(addr));
}
__device__ __forceinline__ void mma16816(float* c, const uint32_t* a, const uint32_t* b) {
    asm volatile(
        "mma.sync.aligned.m16n8k16.row.col.f32.f16.f16.f32 "
        "{%0,%1,%2,%3},{%4,%5,%6,%7},{%8,%9},{%0,%1,%2,%3};"
        : "+f"(c[0]), "+f"(c[1]), "+f"(c[2]), "+f"(c[3])
        : "r"(a[0]), "r"(a[1]), "r"(a[2]), "r"(a[3]), "r"(b[0]), "r"(b[1]));
}

// Swizzled byte offset inside one [rows][32 halves] tile (64B rows, 4x16B chunks).
// Chunk c of row m -> c ^ ((m>>1)&3): conflict-free for cp.async stores and
// ldmatrix phases (verified shape, used in both passing kernels).
__device__ __forceinline__ uint32_t swz(int row, int chunk) {
    return (uint32_t)(row * 64 + ((chunk ^ ((row >> 1) & 3)) << 4));
}

__global__ void __launch_bounds__(128)
gemm_f16_kernel(const float* __restrict__ bias, float* __restrict__ out) {
    extern __shared__ __align__(128) char dsm_raw[];
    uint32_t dbase;
    {
        uint32_t a;
        asm("{ .reg .u64 t; cvta.to.shared.u64 t, %1; cvt.u32.u64 %0, t; }"
            : "=r"(a) : "l"(dsm_raw));
        dbase = (a + 1023u) & ~1023u;
    }

    // 32 m-tiles fast, 86 n-tiles slow: one co-resident set (296 CTAs) reuses
    // A (32MB) fully and ~9 B slabs (9MB) from L2.
    const int pm = blockIdx.x & 31;
    const int pn = blockIdx.x >> 5;
    const int m0 = pm * BM, n0 = pn * BN;

    const int tid = threadIdx.x;
    const int warp = tid >> 5, lane = tid & 31;
    const int wm = (warp >> 1) * 64;  // 0 or 64
    const int wn = (warp & 1) * 64;   // 0 or 64

    const __half* gA = g_xh + (size_t)m0 * KD;
    const __half* gB = g_wh + (size_t)n0 * KD;

    // cp.async: per stage A = 512 chunks, B = 512 chunks; 128 threads -> 4+4 each
    const int rA = tid >> 2;        // 0..31
    const int cC = tid & 3;         // chunk col 0..3

    auto load_stage = [&](int kt) {
        const uint32_t sb = dbase + (kt % STAGES) * STAGE_BYTES;
        const int k0 = kt * BK;
#pragma unroll
        for (int i = 0; i < 4; i++) {
            cp_async16(sb + swz(rA + i * 32, cC),
                       gA + (size_t)(rA + i * 32) * KD + k0 + cC * 8);
        }
        const uint32_t bb = sb + A_BYTES;
#pragma unroll
        for (int i = 0; i < 4; i++) {
            cp_async16(bb + swz(rA + i * 32, cC),
                       gB + (size_t)(rA + i * 32) * KD + k0 + cC * 8);
        }
        cp_commit();
    };

    float acc[4][8][4];
#pragma unroll
    for (int i = 0; i < 4; i++)
#pragma unroll
        for (int j = 0; j < 8; j++)
#pragma unroll
            for (int v = 0; v < 4; v++) acc[i][j][v] = 0.f;

    // Prologue: stages 0..S-2 in flight (S-1 committed groups)
    for (int p = 0; p < STAGES - 1; p++) load_stage(p);

    // ldmatrix lane->address mappings (constant across k loop)
    const int a_row = lane & 15;
    const int a_chx = lane >> 4;
    const int b_row = ((lane >> 4) << 3) + (lane & 7);
    const int b_chx = (lane >> 3) & 1;

    for (int kt = 0; kt < KT; kt++) {
        // pending = S-1 groups; wait to S-2 => stage kt complete
        asm volatile("cp.async.wait_group %0;" :: "n"(STAGES - 2) : "memory");
        __syncthreads();
        // issue next load AFTER the sync (its target buffer was read in iter kt-1)
        if (kt + STAGES - 1 < KT) load_stage(kt + STAGES - 1);
        else cp_commit();  // empty group keeps pending-count arithmetic uniform

        const uint32_t sb = dbase + (kt % STAGES) * STAGE_BYTES;
        const uint32_t bb = sb + A_BYTES;
#pragma unroll
        for (int ks = 0; ks < 2; ks++) {  // two k16 steps in BK=32
            uint32_t a[4][4];
#pragma unroll
            for (int mf = 0; mf < 4; mf++)
                ldm_x4(a[mf], sb + swz(wm + mf * 16 + a_row, ks * 2 + a_chx));
            uint32_t b[8][2];
#pragma unroll
            for (int nf2 = 0; nf2 < 4; nf2++) {
                uint32_t r[4];
                ldm_x4(r, bb + swz(wn + nf2 * 16 + b_row, ks * 2 + b_chx));
                b[nf2 * 2][0] = r[0];     b[nf2 * 2][1] = r[1];
                b[nf2 * 2 + 1][0] = r[2]; b[nf2 * 2 + 1][1] = r[3];
            }
#pragma unroll
            for (int mf = 0; mf < 4; mf++)
#pragma unroll
                for (int nf = 0; nf < 8; nf++) mma16816(acc[mf][nf], a[mf], b[nf]);
        }
    }

    // Epilogue: + bias, fp32 out (frag (mf,nf): rows +{0,8}, cols lane%4*2)
#pragma unroll
    for (int nf = 0; nf < 8; nf++) {
        const int n = n0 + wn + nf * 8 + ((lane & 3) << 1);
        const float2 bv = *reinterpret_cast<const float2*>(bias + n);
#pragma unroll
        for (int mf = 0; mf < 4; mf++) {
            const int m = m0 + wm + mf * 16 + (lane >> 2);
            float2 v0 = make_float2(acc[mf][nf][0] + bv.x, acc[mf][nf][1] + bv.y);
            float2 v1 = make_float2(acc[mf][nf][2] + bv.x, acc[mf][nf][3] + bv.y);
            *reinterpret_cast<float2*>(out + (size_t)m * ND + n) = v0;
            *reinterpret_cast<float2*>(out + (size_t)(m + 8) * ND + n) = v1;
        }
    }
}

// ---------------------------------------------------------------------------
extern "C" void kernel_launch(void* const* d_in, const int* in_sizes, int n_in,
                              void* d_out, int out_size) {
    const float* x     = (const float*)d_in[0];
    const int*   w     = (const int*)d_in[1];
    const float* scale = (const float*)d_in[2];
    const float* off   = (const float*)d_in[3];
    const float* bias  = (const float*)d_in[4];
    float* out = (float*)d_out;

    prep_x_kernel<<<2048, 256>>>(x);
    prep_w_kernel<<<4096, 256>>>(w, scale, off);

    const int dyn_smem = STAGES * STAGE_BYTES + 1024;  // 82944 B -> 2 CTAs/SM
    cudaFuncSetAttribute(gemm_f16_kernel, cudaFuncAttributeMaxDynamicSharedMemorySize, dyn_smem);
    gemm_f16_kernel<<<(MD / BM) * (ND / BN), 128, dyn_smem>>>(bias, out);
}